// round 7
// baseline (speedup 1.0000x reference)
#include <cuda_runtime.h>

#define NJ 24
#define TB 16
#define NP 8                        // sample pairs per block (f32x2 packing)
#define NPH 4                       // pairs handled per thread (NP / 2 phases)
#define NSLOT 68
#define PSTR (NJ * NSLOT + 2)       // 1634 float2 per pair-slot (pad: ph-groups on different banks)
#define NTHREADS 768
#define SMEM_BYTES (2 * NP * PSTR * 8)   // 209152 B (two float2 buffers)

typedef unsigned long long ull;

// ---- f32x2 packed helpers (ptxas never emits FFMA2 from C++) ----
__device__ __forceinline__ ull pack2(float lo, float hi) {
    ull r; asm("mov.b64 %0, {%1, %2};" : "=l"(r) : "f"(lo), "f"(hi)); return r;
}
__device__ __forceinline__ ull fma2(ull a, ull b, ull c) {
    ull d; asm("fma.rn.f32x2 %0, %1, %2, %3;" : "=l"(d) : "l"(a), "l"(b), "l"(c)); return d;
}
__device__ __forceinline__ ull add2(ull a, ull b) {
    ull d; asm("add.rn.f32x2 %0, %1, %2;" : "=l"(d) : "l"(a), "l"(b)); return d;
}
__device__ __forceinline__ ull relu2(ull v) {
    float lo, hi;
    asm("mov.b64 {%0, %1}, %2;" : "=f"(lo), "=f"(hi) : "l"(v));
    return pack2(fmaxf(lo, 0.f), fmaxf(hi, 0.f));
}

// Kinematic-tree adjacency (self + parent + children), CSR. 70 nonzeros.
__constant__ int cPTR[NJ + 1] = {0,4,7,10,13,16,19,22,25,28,33,35,37,40,43,46,48,51,54,57,60,63,66,68,70};
__constant__ int cCOL[70] = {
    0,1,2,3,  1,0,4,  2,0,5,  3,0,6,  4,1,7,  5,2,8,  6,3,9,  7,4,10,
    8,5,11,  9,6,12,13,14,  10,7,  11,8,  12,9,15,  13,9,16,  14,9,17,
    15,12,  16,13,18,  17,14,19,  18,16,20,  19,17,21,  20,18,22,
    21,19,23,  22,20,  23,21};

// Duplicated weights: each scalar w stored as adjacent pair (w, w) so the
// linear inner loop needs zero pack/mov ops. Layout [n][l][2*j .. 2*j+1].
__device__ float g_w0d[NJ * 13 * 64 * 2];    //  39936 floats
__device__ float g_w1d[NJ * 64 * 64 * 2];    // 196608
__device__ float g_w2d[NJ * 64 * 64 * 2];    // 196608
__device__ float g_w3d[NJ * 64 * 68 * 2];    // 208896 (cols 65..67 zero)

__global__ void prep_dup_kernel(const float* __restrict__ w, float* __restrict__ wd,
                                int rows, int dout, int dout_pad) {
    int idx = blockIdx.x * blockDim.x + threadIdx.x;   // over rows * dout_pad
    if (idx < rows * dout_pad) {
        int j = idx % dout_pad;
        int r = idx / dout_pad;
        float v = (j < dout) ? w[r * dout + j] : 0.0f;
        wd[(r * dout_pad + j) * 2]     = v;
        wd[(r * dout_pad + j) * 2 + 1] = v;
    }
}

// Per-node linear on pair-packed activations, duplicated weights.
// Work item = (n, jv, ph): joint n, 4 output cols jv*4.., pairs [ph*NPH, ..+NPH).
// Adjacent threads (2jv, 2jv+1) share weight addresses -> LDG dedup in L1tex.
template <int DIN, int DOUT>
__device__ __forceinline__ void linear2(const float* __restrict__ Wd,
                                        const float2* __restrict__ A,
                                        float2* __restrict__ Bf, int tid) {
    constexpr int JV = DOUT / 4;
    for (int t = tid; t < NJ * JV * 2; t += NTHREADS) {
        int n = t / (JV * 2);
        int q = t - n * (JV * 2);
        int jv = q >> 1;
        int ph = q & 1;
        const float* wp = Wd + (n * DIN) * (DOUT * 2) + jv * 8;
        const float2* ap = A + n * NSLOT + ph * (NPH * PSTR);
        ull acc[NPH][4];
#pragma unroll
        for (int p = 0; p < NPH; p++) {
            acc[p][0] = 0ull; acc[p][1] = 0ull; acc[p][2] = 0ull; acc[p][3] = 0ull;
        }
#pragma unroll 4
        for (int l = 0; l < DIN; l++) {
            // (wx,wx,wy,wy) and (wz,wz,ww,ww) — pre-duplicated, no packs.
            ulonglong2 wab = *reinterpret_cast<const ulonglong2*>(wp + l * (DOUT * 2));
            ulonglong2 wcd = *reinterpret_cast<const ulonglong2*>(wp + l * (DOUT * 2) + 4);
#pragma unroll
            for (int p = 0; p < NPH; p++) {
                ull a2 = *reinterpret_cast<const ull*>(ap + p * PSTR + l);  // LDS.64, 2-way bcast
                acc[p][0] = fma2(a2, wab.x, acc[p][0]);
                acc[p][1] = fma2(a2, wab.y, acc[p][1]);
                acc[p][2] = fma2(a2, wcd.x, acc[p][2]);
                acc[p][3] = fma2(a2, wcd.y, acc[p][3]);
            }
        }
        float2* op = Bf + n * NSLOT + jv * 4 + ph * (NPH * PSTR);
#pragma unroll
        for (int p = 0; p < NPH; p++) {
            ulonglong2 v0; v0.x = acc[p][0]; v0.y = acc[p][1];
            ulonglong2 v1; v1.x = acc[p][2]; v1.y = acc[p][3];
            *reinterpret_cast<ulonglong2*>(op + p * PSTR)     = v0;  // STS.128
            *reinterpret_cast<ulonglong2*>(op + p * PSTR + 2) = v1;
        }
    }
}

// Sparse adjacency + bias (+relu) on pair-packed data. Work item = (n, jv, ph).
__device__ __forceinline__ void adj2(const float* __restrict__ aw,
                                     const float* __restrict__ bias,
                                     const float2* __restrict__ Bf,
                                     float2* __restrict__ Aout,
                                     int tid, bool relu) {
    for (int t = tid; t < NJ * 32; t += NTHREADS) {
        int n = t >> 5;
        int q = t & 31;
        int jv = q >> 1;
        int ph = q & 1;
        int pofs = ph * (NPH * PSTR);
        float4 bbv = *reinterpret_cast<const float4*>(bias + jv * 4);
        ull acc[NPH][4];
#pragma unroll
        for (int p = 0; p < NPH; p++) {
            acc[p][0] = 0ull; acc[p][1] = 0ull; acc[p][2] = 0ull; acc[p][3] = 0ull;
        }
        int e1 = cPTR[n + 1];
        for (int e = cPTR[n]; e < e1; e++) {
            int m = cCOL[e];
            float v = aw[n * NJ + m];
            ull v2 = pack2(v, v);
            const float2* bp = Bf + m * NSLOT + jv * 4 + pofs;
#pragma unroll
            for (int p = 0; p < NPH; p++) {
                ulonglong2 h0 = *reinterpret_cast<const ulonglong2*>(bp + p * PSTR);      // LDS.128
                ulonglong2 h1 = *reinterpret_cast<const ulonglong2*>(bp + p * PSTR + 2);
                acc[p][0] = fma2(v2, h0.x, acc[p][0]);
                acc[p][1] = fma2(v2, h0.y, acc[p][1]);
                acc[p][2] = fma2(v2, h1.x, acc[p][2]);
                acc[p][3] = fma2(v2, h1.y, acc[p][3]);
            }
        }
        ull bb0 = pack2(bbv.x, bbv.x), bb1 = pack2(bbv.y, bbv.y);
        ull bb2 = pack2(bbv.z, bbv.z), bb3 = pack2(bbv.w, bbv.w);
        float2* op = Aout + n * NSLOT + jv * 4 + pofs;
#pragma unroll
        for (int p = 0; p < NPH; p++) {
            ull r0 = add2(acc[p][0], bb0);
            ull r1 = add2(acc[p][1], bb1);
            ull r2 = add2(acc[p][2], bb2);
            ull r3 = add2(acc[p][3], bb3);
            if (relu) { r0 = relu2(r0); r1 = relu2(r1); r2 = relu2(r2); r3 = relu2(r3); }
            ulonglong2 v0; v0.x = r0; v0.y = r1;
            ulonglong2 v1; v1.x = r2; v1.y = r3;
            *reinterpret_cast<ulonglong2*>(op + p * PSTR)     = v0;
            *reinterpret_cast<ulonglong2*>(op + p * PSTR + 2) = v1;
        }
    }
}

// Final adjacency + bias, unpack pairs and write straight to gmem (dout=65).
__device__ __forceinline__ void adj_final2(const float* __restrict__ aw,
                                           const float* __restrict__ bias,
                                           const float2* __restrict__ Bf,
                                           float* __restrict__ outp,
                                           int nvalid, int tid) {
    for (int t = tid; t < NJ * 65 * 2; t += NTHREADS) {
        int half = t / (NJ * 65);          // 0 or 1
        int r = t - half * (NJ * 65);
        int n = r / 65;
        int j = r - n * 65;
        int pofs = half * (NPH * PSTR);
        float bb = bias[j];
        float ax[NPH], ay[NPH];
#pragma unroll
        for (int p = 0; p < NPH; p++) { ax[p] = bb; ay[p] = bb; }
        int e1 = cPTR[n + 1];
        for (int e = cPTR[n]; e < e1; e++) {
            int m = cCOL[e];
            float v = aw[n * NJ + m];
            const float2* bp = Bf + m * NSLOT + j + pofs;
#pragma unroll
            for (int p = 0; p < NPH; p++) {
                float2 h = bp[p * PSTR];
                ax[p] = fmaf(v, h.x, ax[p]);
                ay[p] = fmaf(v, h.y, ay[p]);
            }
        }
#pragma unroll
        for (int p = 0; p < NPH; p++) {
            int s0 = 2 * (half * NPH + p), s1 = s0 + 1;
            if (s0 < nvalid) outp[(size_t)s0 * (NJ * 65) + n * 65 + j] = ax[p];
            if (s1 < nvalid) outp[(size_t)s1 * (NJ * 65) + n * 65 + j] = ay[p];
        }
    }
}

__global__ __launch_bounds__(NTHREADS, 1)
void gnn_fused(const float* __restrict__ x,
               const float* __restrict__ aw0, const float* __restrict__ aw1,
               const float* __restrict__ aw2, const float* __restrict__ aw3,
               const float* __restrict__ b0, const float* __restrict__ b1,
               const float* __restrict__ b2, const float* __restrict__ b3,
               float* __restrict__ out, int Btot) {
    extern __shared__ float2 smem[];
    float2* Abuf = smem;
    float2* Bbuf = smem + NP * PSTR;
    int tid = threadIdx.x;
    int B0 = blockIdx.x * TB;
    int nvalid = Btot - B0;
    if (nvalid > TB) nvalid = TB;

    // Load x tile into pair-interleaved layout, apply root mask (joint 0 -> 0).
    float* dst = reinterpret_cast<float*>(Abuf);
    for (int i = tid; i < TB * NJ * 13; i += NTHREADS) {
        int s = i / (NJ * 13);
        int r = i - s * (NJ * 13);
        int n = r / 13;
        int c = r - n * 13;
        float v = 0.0f;
        if (s < nvalid && n != 0) v = x[(size_t)B0 * (NJ * 13) + i];
        dst[((s >> 1) * PSTR + n * NSLOT + c) * 2 + (s & 1)] = v;
    }
    __syncthreads();

    linear2<13, 64>(g_w0d, Abuf, Bbuf, tid);  __syncthreads();
    adj2(aw0, b0, Bbuf, Abuf, tid, true);     __syncthreads();
    linear2<64, 64>(g_w1d, Abuf, Bbuf, tid);  __syncthreads();
    adj2(aw1, b1, Bbuf, Abuf, tid, true);     __syncthreads();
    linear2<64, 64>(g_w2d, Abuf, Bbuf, tid);  __syncthreads();
    adj2(aw2, b2, Bbuf, Abuf, tid, true);     __syncthreads();
    linear2<64, 68>(g_w3d, Abuf, Bbuf, tid);  __syncthreads();
    adj_final2(aw3, b3, Bbuf, out + (size_t)B0 * (NJ * 65), nvalid, tid);
}

extern "C" void kernel_launch(void* const* d_in, const int* in_sizes, int n_in,
                              void* d_out, int out_size) {
    // Identify inputs by element count (robust to metadata ordering).
    const float* x = nullptr;
    const float* w[4] = {nullptr, nullptr, nullptr, nullptr};
    const float* aw[4] = {nullptr, nullptr, nullptr, nullptr};
    const float* b[4] = {nullptr, nullptr, nullptr, nullptr};
    int iw12 = 1, iaw = 0, ib = 0;
    int Btot = 0;
    for (int i = 0; i < n_in; i++) {
        int sz = in_sizes[i];
        const float* p = (const float*)d_in[i];
        if (sz == 24 * 13 * 64) {
            w[0] = p;
        } else if (sz == 24 * 64 * 64) {
            if (iw12 < 3) w[iw12++] = p;
        } else if (sz == 24 * 64 * 65) {
            w[3] = p;
        } else if (sz == 24 * 24) {
            if (iaw < 4) aw[iaw++] = p;
        } else if (sz == 64) {
            if (ib < 3) b[ib++] = p;
        } else if (sz == 65) {
            b[3] = p;
        } else {
            x = p;
            Btot = sz / (NJ * 13);
        }
    }

    (void)cudaFuncSetAttribute(gnn_fused, cudaFuncAttributeMaxDynamicSharedMemorySize, SMEM_BYTES);

    // Weight duplication prep (device globals resolved on GPU side of the launch).
    float* w0d; cudaGetSymbolAddress((void**)&w0d, g_w0d);
    float* w1d; cudaGetSymbolAddress((void**)&w1d, g_w1d);
    float* w2d; cudaGetSymbolAddress((void**)&w2d, g_w2d);
    float* w3d; cudaGetSymbolAddress((void**)&w3d, g_w3d);
    prep_dup_kernel<<<(NJ * 13 * 64 + 255) / 256, 256>>>(w[0], w0d, NJ * 13, 64, 64);
    prep_dup_kernel<<<(NJ * 64 * 64 + 255) / 256, 256>>>(w[1], w1d, NJ * 64, 64, 64);
    prep_dup_kernel<<<(NJ * 64 * 64 + 255) / 256, 256>>>(w[2], w2d, NJ * 64, 64, 64);
    prep_dup_kernel<<<(NJ * 64 * 68 + 255) / 256, 256>>>(w[3], w3d, NJ * 64, 65, 68);

    int blocks = (Btot + TB - 1) / TB;
    gnn_fused<<<blocks, NTHREADS, SMEM_BYTES>>>(
        x,
        aw[0], aw[1], aw[2], aw[3],
        b[0], b[1], b[2], b[3],
        (float*)d_out, Btot);
}

// round 8
// speedup vs baseline: 2.2107x; 2.2107x over previous
#include <cuda_runtime.h>
#include <cuda_bf16.h>

#define NJ 24
#define TB 16
#define NTHREADS 768
#define ACT_K 72            // padded bf16 row (bank-conflict-free ldmatrix: 144B stride)
#define LIN_C 76            // padded fp32 row
#define ACT_BYTES (NJ * 2 * TB * ACT_K * 2)         // 110592
#define LIN_BYTES (NJ * TB * LIN_C * 4)             // 116736
#define SMEM_BYTES (ACT_BYTES + LIN_BYTES)          // 227328

typedef unsigned int uint;
typedef unsigned long long ull;

// ---- f32x2 helpers for the adjacency phase ----
__device__ __forceinline__ ull pack2(float lo, float hi) {
    ull r; asm("mov.b64 %0, {%1, %2};" : "=l"(r) : "f"(lo), "f"(hi)); return r;
}
__device__ __forceinline__ ull fma2(ull a, ull b, ull c) {
    ull d; asm("fma.rn.f32x2 %0, %1, %2, %3;" : "=l"(d) : "l"(a), "l"(b), "l"(c)); return d;
}
__device__ __forceinline__ ull add2(ull a, ull b) {
    ull d; asm("add.rn.f32x2 %0, %1, %2;" : "=l"(d) : "l"(a), "l"(b)); return d;
}
__device__ __forceinline__ unsigned smem_u32(const void* p) {
    unsigned r;
    asm("{ .reg .u64 t; cvta.to.shared.u64 t, %1; cvt.u32.u64 %0, t; }" : "=r"(r) : "l"(p));
    return r;
}
__device__ __forceinline__ uint packbf(__nv_bfloat16 a, __nv_bfloat16 b) {
    __nv_bfloat162 t(a, b);             // a = low half
    return *reinterpret_cast<uint*>(&t);
}

// Kinematic-tree adjacency (self + parent + children), CSR. 70 nonzeros.
__constant__ int cPTR[NJ + 1] = {0,4,7,10,13,16,19,22,25,28,33,35,37,40,43,46,48,51,54,57,60,63,66,68,70};
__constant__ int cCOL[70] = {
    0,1,2,3,  1,0,4,  2,0,5,  3,0,6,  4,1,7,  5,2,8,  6,3,9,  7,4,10,
    8,5,11,  9,6,12,13,14,  10,7,  11,8,  12,9,15,  13,9,16,  14,9,17,
    15,12,  16,13,18,  17,14,19,  18,16,20,  19,17,21,  20,18,22,
    21,19,23,  22,20,  23,21};

// Weight fragments in exact mma.m16n8k16 B-operand per-lane order.
// One uint4 per (n, kt, nt, lane): {hi0, hi1, lo0, lo1} bf16x2 pairs.
__device__ uint4 g_wf0[NJ * 1 * 8 * 32];
__device__ uint4 g_wf1[NJ * 4 * 8 * 32];
__device__ uint4 g_wf2[NJ * 4 * 8 * 32];
__device__ uint4 g_wf3[NJ * 4 * 9 * 32];

__global__ void prep_frag(const float* __restrict__ W, uint4* __restrict__ dst,
                          int DIN, int DOUT, int KT, int NT) {
    int idx = blockIdx.x * blockDim.x + threadIdx.x;
    int total = NJ * KT * NT * 32;
    if (idx >= total) return;
    int lane = idx & 31;
    int nt = (idx >> 5) % NT;
    int kt = (idx / (32 * NT)) % KT;
    int n  = idx / (32 * NT * KT);
    int k0 = kt * 16 + (lane & 3) * 2;
    int nc = nt * 8 + (lane >> 2);

    float w[4];
    int ks[4] = {k0, k0 + 1, k0 + 8, k0 + 9};
#pragma unroll
    for (int i = 0; i < 4; i++)
        w[i] = (ks[i] < DIN && nc < DOUT) ? W[(n * DIN + ks[i]) * DOUT + nc] : 0.0f;

    __nv_bfloat16 h[4], l[4];
#pragma unroll
    for (int i = 0; i < 4; i++) {
        h[i] = __float2bfloat16_rn(w[i]);
        l[i] = __float2bfloat16_rn(w[i] - __bfloat162float(h[i]));
    }
    uint4 o;
    o.x = packbf(h[0], h[1]);
    o.y = packbf(h[2], h[3]);
    o.z = packbf(l[0], l[1]);
    o.w = packbf(l[2], l[3]);
    dst[idx] = o;
}

#define MMA_BF16(C, A0, A1, A2, A3, B0, B1)                                     \
    asm volatile(                                                               \
        "mma.sync.aligned.m16n8k16.row.col.f32.bf16.bf16.f32 "                  \
        "{%0,%1,%2,%3}, {%4,%5,%6,%7}, {%8,%9}, {%0,%1,%2,%3};"                 \
        : "+f"((C)[0]), "+f"((C)[1]), "+f"((C)[2]), "+f"((C)[3])                \
        : "r"(A0), "r"(A1), "r"(A2), "r"(A3), "r"(B0), "r"(B1))

// Per-joint linear via tensor cores: LIN[n][m][col] = sum_k ACT(n,m,k) * W(n,k,col)
// Warp w handles joint n = w. 3-term bf16 split: AhWh + AlWh + AhWl, fp32 acc.
template <int KT, int NT>
__device__ __forceinline__ void linear_mma(const uint4* __restrict__ wf,
                                           const __nv_bfloat16* __restrict__ ACT,
                                           float* __restrict__ LIN, int tid) {
    int n = tid >> 5;
    int lane = tid & 31;
    float c[NT][4];
#pragma unroll
    for (int i = 0; i < NT; i++) { c[i][0] = c[i][1] = c[i][2] = c[i][3] = 0.f; }

    int rowm = lane & 15;
    int kofs = (lane >> 4) << 3;

#pragma unroll
    for (int kt = 0; kt < KT; kt++) {
        uint ah0, ah1, ah2, ah3, al0, al1, al2, al3;
        unsigned addrh = smem_u32(ACT + ((n * 2 + 0) * TB + rowm) * ACT_K + kt * 16 + kofs);
        unsigned addrl = smem_u32(ACT + ((n * 2 + 1) * TB + rowm) * ACT_K + kt * 16 + kofs);
        asm volatile("ldmatrix.sync.aligned.m8n8.x4.shared.b16 {%0,%1,%2,%3}, [%4];"
                     : "=r"(ah0), "=r"(ah1), "=r"(ah2), "=r"(ah3) : "r"(addrh));
        asm volatile("ldmatrix.sync.aligned.m8n8.x4.shared.b16 {%0,%1,%2,%3}, [%4];"
                     : "=r"(al0), "=r"(al1), "=r"(al2), "=r"(al3) : "r"(addrl));

        const uint4* wp = wf + (size_t)((n * KT + kt) * NT) * 32 + lane;
        uint4 wcur = wp[0];
#pragma unroll
        for (int nt = 0; nt < NT; nt++) {
            uint4 wnext = (nt + 1 < NT) ? wp[(nt + 1) * 32] : wcur;   // 1-deep prefetch
            MMA_BF16(c[nt], ah0, ah1, ah2, ah3, wcur.x, wcur.y);      // Ahi * Whi
            MMA_BF16(c[nt], al0, al1, al2, al3, wcur.x, wcur.y);      // Alo * Whi
            MMA_BF16(c[nt], ah0, ah1, ah2, ah3, wcur.z, wcur.w);      // Ahi * Wlo
            wcur = wnext;
        }
    }

    // Epilogue: fragment -> LIN[n][m][col]
    int m0 = lane >> 2;
    int cb = (lane & 3) * 2;
#pragma unroll
    for (int nt = 0; nt < NT; nt++) {
        int col = nt * 8 + cb;
        *reinterpret_cast<float2*>(&LIN[(n * TB + m0) * LIN_C + col]) =
            make_float2(c[nt][0], c[nt][1]);
        *reinterpret_cast<float2*>(&LIN[(n * TB + m0 + 8) * LIN_C + col]) =
            make_float2(c[nt][2], c[nt][3]);
    }
}

// Adjacency + bias + relu on fp32 LIN, emit split bf16 hi/lo into ACT.
// Thread = (joint n, column pair j2). One warp = one joint.
__device__ __forceinline__ void adj_mid(const float* __restrict__ aw,
                                        const float* __restrict__ bias,
                                        const float* __restrict__ LIN,
                                        __nv_bfloat16* __restrict__ ACT, int tid) {
    int n = tid >> 5;
    int j2 = tid & 31;
    ull b2 = pack2(bias[2 * j2], bias[2 * j2 + 1]);
    ull acc[TB];
#pragma unroll
    for (int s = 0; s < TB; s++) acc[s] = 0ull;

    int e1 = cPTR[n + 1];
    for (int e = cPTR[n]; e < e1; e++) {
        int mj = cCOL[e];
        float v = aw[n * NJ + mj];
        ull v2 = pack2(v, v);
        const float* bp = LIN + (mj * TB) * LIN_C + 2 * j2;
#pragma unroll
        for (int s = 0; s < TB; s++) {
            ull h = *reinterpret_cast<const ull*>(bp + s * LIN_C);
            acc[s] = fma2(v2, h, acc[s]);
        }
    }
#pragma unroll
    for (int s = 0; s < TB; s++) {
        ull r = add2(acc[s], b2);
        float f0, f1;
        asm("mov.b64 {%0, %1}, %2;" : "=f"(f0), "=f"(f1) : "l"(r));
        f0 = fmaxf(f0, 0.f);
        f1 = fmaxf(f1, 0.f);
        __nv_bfloat16 h0 = __float2bfloat16_rn(f0);
        __nv_bfloat16 h1 = __float2bfloat16_rn(f1);
        __nv_bfloat16 l0 = __float2bfloat16_rn(f0 - __bfloat162float(h0));
        __nv_bfloat16 l1 = __float2bfloat16_rn(f1 - __bfloat162float(h1));
        uint* dh = reinterpret_cast<uint*>(ACT + ((n * 2 + 0) * TB + s) * ACT_K + 2 * j2);
        uint* dl = reinterpret_cast<uint*>(ACT + ((n * 2 + 1) * TB + s) * ACT_K + 2 * j2);
        *dh = packbf(h0, h1);
        *dl = packbf(l0, l1);
    }
}

// Final adjacency + bias, write to gmem (dout = 65).
__device__ __forceinline__ void adj_fin(const float* __restrict__ aw,
                                        const float* __restrict__ bias,
                                        const float* __restrict__ LIN,
                                        float* __restrict__ outp,
                                        int nvalid, int tid) {
    for (int t = tid; t < NJ * 65; t += NTHREADS) {
        int n = t / 65;
        int j = t - n * 65;
        float bb = bias[j];
        float acc[TB];
#pragma unroll
        for (int s = 0; s < TB; s++) acc[s] = bb;
        int e1 = cPTR[n + 1];
        for (int e = cPTR[n]; e < e1; e++) {
            int mj = cCOL[e];
            float v = aw[n * NJ + mj];
            const float* bp = LIN + (mj * TB) * LIN_C + j;
#pragma unroll
            for (int s = 0; s < TB; s++)
                acc[s] = fmaf(v, bp[s * LIN_C], acc[s]);
        }
#pragma unroll
        for (int s = 0; s < TB; s++)
            if (s < nvalid) outp[(size_t)s * (NJ * 65) + n * 65 + j] = acc[s];
    }
}

__global__ __launch_bounds__(NTHREADS, 1)
void gnn_fused(const float* __restrict__ x,
               const float* __restrict__ aw0, const float* __restrict__ aw1,
               const float* __restrict__ aw2, const float* __restrict__ aw3,
               const float* __restrict__ b0, const float* __restrict__ b1,
               const float* __restrict__ b2, const float* __restrict__ b3,
               float* __restrict__ out, int Btot) {
    extern __shared__ char smraw[];
    __nv_bfloat16* ACT = reinterpret_cast<__nv_bfloat16*>(smraw);
    float* LIN = reinterpret_cast<float*>(smraw + ACT_BYTES);
    int tid = threadIdx.x;
    int B0 = blockIdx.x * TB;
    int nvalid = Btot - B0;
    if (nvalid > TB) nvalid = TB;

    // Load x tile, mask root joint, split to bf16 hi/lo; zero-pad cols 13..15 (layer0 K-tile).
    for (int i = tid; i < TB * NJ * 16; i += NTHREADS) {
        int s = i / (NJ * 16);
        int r = i - s * (NJ * 16);
        int n = r >> 4;
        int c = r & 15;
        float v = 0.0f;
        if (s < nvalid && n != 0 && c < 13)
            v = x[((size_t)(B0 + s) * NJ + n) * 13 + c];
        __nv_bfloat16 h = __float2bfloat16_rn(v);
        __nv_bfloat16 l = __float2bfloat16_rn(v - __bfloat162float(h));
        ACT[((n * 2 + 0) * TB + s) * ACT_K + c] = h;
        ACT[((n * 2 + 1) * TB + s) * ACT_K + c] = l;
    }
    __syncthreads();

    linear_mma<1, 8>(g_wf0, ACT, LIN, tid);  __syncthreads();
    adj_mid(aw0, b0, LIN, ACT, tid);         __syncthreads();
    linear_mma<4, 8>(g_wf1, ACT, LIN, tid);  __syncthreads();
    adj_mid(aw1, b1, LIN, ACT, tid);         __syncthreads();
    linear_mma<4, 8>(g_wf2, ACT, LIN, tid);  __syncthreads();
    adj_mid(aw2, b2, LIN, ACT, tid);         __syncthreads();
    linear_mma<4, 9>(g_wf3, ACT, LIN, tid);  __syncthreads();
    adj_fin(aw3, b3, LIN, out + (size_t)B0 * (NJ * 65), nvalid, tid);
}

extern "C" void kernel_launch(void* const* d_in, const int* in_sizes, int n_in,
                              void* d_out, int out_size) {
    // Identify inputs by element count (robust to metadata ordering).
    const float* x = nullptr;
    const float* w[4] = {nullptr, nullptr, nullptr, nullptr};
    const float* aw[4] = {nullptr, nullptr, nullptr, nullptr};
    const float* b[4] = {nullptr, nullptr, nullptr, nullptr};
    int iw12 = 1, iaw = 0, ib = 0;
    int Btot = 0;
    for (int i = 0; i < n_in; i++) {
        int sz = in_sizes[i];
        const float* p = (const float*)d_in[i];
        if (sz == 24 * 13 * 64) {
            w[0] = p;
        } else if (sz == 24 * 64 * 64) {
            if (iw12 < 3) w[iw12++] = p;
        } else if (sz == 24 * 64 * 65) {
            w[3] = p;
        } else if (sz == 24 * 24) {
            if (iaw < 4) aw[iaw++] = p;
        } else if (sz == 64) {
            if (ib < 3) b[ib++] = p;
        } else if (sz == 65) {
            b[3] = p;
        } else {
            x = p;
            Btot = sz / (NJ * 13);
        }
    }

    (void)cudaFuncSetAttribute(gnn_fused, cudaFuncAttributeMaxDynamicSharedMemorySize, SMEM_BYTES);

    uint4 *wf0, *wf1, *wf2, *wf3;
    cudaGetSymbolAddress((void**)&wf0, g_wf0);
    cudaGetSymbolAddress((void**)&wf1, g_wf1);
    cudaGetSymbolAddress((void**)&wf2, g_wf2);
    cudaGetSymbolAddress((void**)&wf3, g_wf3);

    prep_frag<<<(NJ * 1 * 8 * 32 + 255) / 256, 256>>>(w[0], wf0, 13, 64, 1, 8);
    prep_frag<<<(NJ * 4 * 8 * 32 + 255) / 256, 256>>>(w[1], wf1, 64, 64, 4, 8);
    prep_frag<<<(NJ * 4 * 8 * 32 + 255) / 256, 256>>>(w[2], wf2, 64, 64, 4, 8);
    prep_frag<<<(NJ * 4 * 9 * 32 + 255) / 256, 256>>>(w[3], wf3, 64, 65, 4, 9);

    int blocks = (Btot + TB - 1) / TB;
    gnn_fused<<<blocks, NTHREADS, SMEM_BYTES>>>(
        x,
        aw[0], aw[1], aw[2], aw[3],
        b[0], b[1], b[2], b[3],
        (float*)d_out, Btot);
}

// round 10
// speedup vs baseline: 3.0458x; 1.3778x over previous
#include <cuda_runtime.h>
#include <cuda_fp16.h>

#define NJ 24
#define TB 32                // samples per block (2 mma M-tiles)
#define NTHREADS 768
#define ACT_K 72             // padded fp16 row: 144 B stride, 16B-aligned
#define LIN_K 72
#define ACT_BYTES (NJ * TB * ACT_K * 2)     // 110592
#define LIN_BYTES (NJ * TB * LIN_K * 2)     // 110592
#define SMEM_BYTES (ACT_BYTES + LIN_BYTES)  // 221184

typedef unsigned int uint;

__device__ __forceinline__ unsigned smem_u32(const void* p) {
    unsigned r;
    asm("{ .reg .u64 t; cvta.to.shared.u64 t, %1; cvt.u32.u64 %0, t; }" : "=r"(r) : "l"(p));
    return r;
}
__device__ __forceinline__ uint packh(__half a, __half b) {
    __half2 t = __halves2half2(a, b);
    return *reinterpret_cast<uint*>(&t);
}

// Kinematic-tree adjacency (self + parent + children), CSR. 70 nonzeros.
__constant__ int cPTR[NJ + 1] = {0,4,7,10,13,16,19,22,25,28,33,35,37,40,43,46,48,51,54,57,60,63,66,68,70};
__constant__ int cCOL[70] = {
    0,1,2,3,  1,0,4,  2,0,5,  3,0,6,  4,1,7,  5,2,8,  6,3,9,  7,4,10,
    8,5,11,  9,6,12,13,14,  10,7,  11,8,  12,9,15,  13,9,16,  14,9,17,
    15,12,  16,13,18,  17,14,19,  18,16,20,  19,17,21,  20,18,22,
    21,19,23,  22,20,  23,21};

// Weight fragments in mma.m16n8k16 B-operand per-lane order.
// uint4 per (n, kt, nt, lane): {hi0|hi1, hi2|hi3, lo0|lo1, lo2|lo3} fp16x2.
__device__ uint4 g_wf0[NJ * 1 * 8 * 32];
__device__ uint4 g_wf1[NJ * 4 * 8 * 32];
__device__ uint4 g_wf2[NJ * 4 * 8 * 32];
__device__ uint4 g_wf3[NJ * 4 * 9 * 32];

__global__ void prep_frag(const float* __restrict__ W, uint4* __restrict__ dst,
                          int DIN, int DOUT, int KT, int NT) {
    int idx = blockIdx.x * blockDim.x + threadIdx.x;
    int total = NJ * KT * NT * 32;
    if (idx >= total) return;
    int lane = idx & 31;
    int nt = (idx >> 5) % NT;
    int kt = (idx / (32 * NT)) % KT;
    int n  = idx / (32 * NT * KT);
    int k0 = kt * 16 + (lane & 3) * 2;
    int nc = nt * 8 + (lane >> 2);

    float w[4];
    int ks[4] = {k0, k0 + 1, k0 + 8, k0 + 9};
#pragma unroll
    for (int i = 0; i < 4; i++)
        w[i] = (ks[i] < DIN && nc < DOUT) ? W[(n * DIN + ks[i]) * DOUT + nc] : 0.0f;

    __half h[4], l[4];
#pragma unroll
    for (int i = 0; i < 4; i++) {
        h[i] = __float2half_rn(w[i]);
        l[i] = __float2half_rn(w[i] - __half2float(h[i]));
    }
    uint4 o;
    o.x = packh(h[0], h[1]);
    o.y = packh(h[2], h[3]);
    o.z = packh(l[0], l[1]);
    o.w = packh(l[2], l[3]);
    dst[idx] = o;
}

#define MMA_F16(C, A0, A1, A2, A3, B0, B1)                                      \
    asm volatile(                                                               \
        "mma.sync.aligned.m16n8k16.row.col.f32.f16.f16.f32 "                    \
        "{%0,%1,%2,%3}, {%4,%5,%6,%7}, {%8,%9}, {%0,%1,%2,%3};"                 \
        : "+f"((C)[0]), "+f"((C)[1]), "+f"((C)[2]), "+f"((C)[3])                \
        : "r"(A0), "r"(A1), "r"(A2), "r"(A3), "r"(B0), "r"(B1))

// Per-joint linear: LIN[n][s][col] = sum_k ACT[n][s][k] * W[n][k][col].
// Warp = joint. 2 M-tiles (32 samples), weights 2-term fp16 hi+lo, fp32 acc.
// nt processed in chunks of 4 so B-fragments are register-reused across M-tiles.
template <int KT, int NT>
__device__ __forceinline__ void linear_mma(const uint4* __restrict__ wf,
                                           const __half* __restrict__ ACT,
                                           __half* __restrict__ LIN, int tid) {
    int n = tid >> 5;
    int lane = tid & 31;
    int rowm = lane & 15;
    int kofs = (lane >> 4) << 3;
    int m0 = lane >> 2;
    int cb = (lane & 3) * 2;

#pragma unroll
    for (int nt0 = 0; nt0 < NT; nt0 += 4) {
        float c[4][2][4];
#pragma unroll
        for (int i = 0; i < 4; i++)
#pragma unroll
            for (int mt = 0; mt < 2; mt++) {
                c[i][mt][0] = 0.f; c[i][mt][1] = 0.f;
                c[i][mt][2] = 0.f; c[i][mt][3] = 0.f;
            }
#pragma unroll
        for (int kt = 0; kt < KT; kt++) {
            uint a0[4], a1[4];
            unsigned ad0 = smem_u32(ACT + ((n * TB + 0 * 16 + rowm) * ACT_K) + kt * 16 + kofs);
            unsigned ad1 = smem_u32(ACT + ((n * TB + 1 * 16 + rowm) * ACT_K) + kt * 16 + kofs);
            asm volatile("ldmatrix.sync.aligned.m8n8.x4.shared.b16 {%0,%1,%2,%3}, [%4];"
                         : "=r"(a0[0]), "=r"(a0[1]), "=r"(a0[2]), "=r"(a0[3]) : "r"(ad0));
            asm volatile("ldmatrix.sync.aligned.m8n8.x4.shared.b16 {%0,%1,%2,%3}, [%4];"
                         : "=r"(a1[0]), "=r"(a1[1]), "=r"(a1[2]), "=r"(a1[3]) : "r"(ad1));

            const uint4* wp = wf + (size_t)((n * KT + kt) * NT + nt0) * 32 + lane;
#pragma unroll
            for (int ntc = 0; ntc < 4; ntc++) {
                if (nt0 + ntc < NT) {
                    uint4 w = wp[ntc * 32];
                    MMA_F16(c[ntc][0], a0[0], a0[1], a0[2], a0[3], w.x, w.y);  // A * Whi
                    MMA_F16(c[ntc][0], a0[0], a0[1], a0[2], a0[3], w.z, w.w);  // A * Wlo
                    MMA_F16(c[ntc][1], a1[0], a1[1], a1[2], a1[3], w.x, w.y);
                    MMA_F16(c[ntc][1], a1[0], a1[1], a1[2], a1[3], w.z, w.w);
                }
            }
        }
        // Epilogue: fp32 acc -> fp16 LIN
#pragma unroll
        for (int ntc = 0; ntc < 4; ntc++) {
            if (nt0 + ntc < NT) {
                int col = (nt0 + ntc) * 8 + cb;
#pragma unroll
                for (int mt = 0; mt < 2; mt++) {
                    __half2 v0 = __floats2half2_rn(c[ntc][mt][0], c[ntc][mt][1]);
                    __half2 v1 = __floats2half2_rn(c[ntc][mt][2], c[ntc][mt][3]);
                    *reinterpret_cast<__half2*>(&LIN[(n * TB + mt * 16 + m0) * LIN_K + col]) = v0;
                    *reinterpret_cast<__half2*>(&LIN[(n * TB + mt * 16 + m0 + 8) * LIN_K + col]) = v1;
                }
            }
        }
    }
}

// Adjacency + bias + relu: ACT[n][s][c] = relu(sum_m aw[n,m] LIN[m][s][c] + bias[c]).
// Warp = joint n; lane j2 covers cols 2j2, 2j2+1; loops all 32 samples.
__device__ __forceinline__ void adj_mid(const float* __restrict__ aw,
                                        const float* __restrict__ bias,
                                        const __half* __restrict__ LIN,
                                        __half* __restrict__ ACT, int tid) {
    int n = tid >> 5;
    int j2 = tid & 31;
    float b0 = bias[2 * j2], b1 = bias[2 * j2 + 1];

    int deg = cPTR[n + 1] - cPTR[n];
    float vv[5];
    int mm[5];
#pragma unroll
    for (int e = 0; e < 5; e++) {
        int ei = cPTR[n] + ((e < deg) ? e : 0);
        mm[e] = cCOL[ei];
        vv[e] = (e < deg) ? aw[n * NJ + mm[e]] : 0.0f;
    }

#pragma unroll 4
    for (int s = 0; s < TB; s++) {
        float f0 = b0, f1 = b1;
#pragma unroll
        for (int e = 0; e < 5; e++) {
            if (e < deg) {
                __half2 h = *reinterpret_cast<const __half2*>(&LIN[(mm[e] * TB + s) * LIN_K + 2 * j2]);
                float2 f = __half22float2(h);
                f0 = fmaf(vv[e], f.x, f0);
                f1 = fmaf(vv[e], f.y, f1);
            }
        }
        f0 = fmaxf(f0, 0.f);
        f1 = fmaxf(f1, 0.f);
        *reinterpret_cast<__half2*>(&ACT[(n * TB + s) * ACT_K + 2 * j2]) = __floats2half2_rn(f0, f1);
    }
}

// Final adjacency + bias, fp32 out to gmem (dout = 65).
__device__ __forceinline__ void adj_fin(const float* __restrict__ aw,
                                        const float* __restrict__ bias,
                                        const __half* __restrict__ LIN,
                                        float* __restrict__ outp,
                                        int nvalid, int tid) {
    for (int t = tid; t < NJ * 65 * 2; t += NTHREADS) {
        int half = t / (NJ * 65);
        int r = t - half * (NJ * 65);
        int n = r / 65;
        int j = r - n * 65;
        int s0 = half * 16;
        float bb = bias[j];
        float acc[16];
#pragma unroll
        for (int s = 0; s < 16; s++) acc[s] = bb;
        int e1 = cPTR[n + 1];
        for (int e = cPTR[n]; e < e1; e++) {
            int mj = cCOL[e];
            float v = aw[n * NJ + mj];
#pragma unroll
            for (int s = 0; s < 16; s++) {
                float h = __half2float(LIN[(mj * TB + s0 + s) * LIN_K + j]);
                acc[s] = fmaf(v, h, acc[s]);
            }
        }
#pragma unroll
        for (int s = 0; s < 16; s++)
            if (s0 + s < nvalid)
                outp[(size_t)(s0 + s) * (NJ * 65) + n * 65 + j] = acc[s];
    }
}

__global__ __launch_bounds__(NTHREADS, 1)
void gnn_fused(const float* __restrict__ x,
               const float* __restrict__ aw0, const float* __restrict__ aw1,
               const float* __restrict__ aw2, const float* __restrict__ aw3,
               const float* __restrict__ b0, const float* __restrict__ b1,
               const float* __restrict__ b2, const float* __restrict__ b3,
               float* __restrict__ out, int Btot) {
    extern __shared__ char smraw[];
    __half* ACT = reinterpret_cast<__half*>(smraw);
    __half* LIN = reinterpret_cast<__half*>(smraw + ACT_BYTES);
    int tid = threadIdx.x;
    int B0 = blockIdx.x * TB;
    int nvalid = Btot - B0;
    if (nvalid > TB) nvalid = TB;

    // Load x tile -> fp16 ACT; root joint masked; cols 13..15 zero (layer0 K-tile pad).
    for (int i = tid; i < TB * NJ * 16; i += NTHREADS) {
        int s = i / (NJ * 16);
        int r = i - s * (NJ * 16);
        int n = r >> 4;
        int c = r & 15;
        float v = 0.0f;
        if (s < nvalid && n != 0 && c < 13)
            v = x[((size_t)(B0 + s) * NJ + n) * 13 + c];
        ACT[(n * TB + s) * ACT_K + c] = __float2half_rn(v);
    }
    __syncthreads();

    linear_mma<1, 8>(g_wf0, ACT, LIN, tid);  __syncthreads();
    adj_mid(aw0, b0, LIN, ACT, tid);         __syncthreads();
    linear_mma<4, 8>(g_wf1, ACT, LIN, tid);  __syncthreads();
    adj_mid(aw1, b1, LIN, ACT, tid);         __syncthreads();
    linear_mma<4, 8>(g_wf2, ACT, LIN, tid);  __syncthreads();
    adj_mid(aw2, b2, LIN, ACT, tid);         __syncthreads();
    linear_mma<4, 9>(g_wf3, ACT, LIN, tid);  __syncthreads();
    adj_fin(aw3, b3, LIN, out + (size_t)B0 * (NJ * 65), nvalid, tid);
}

extern "C" void kernel_launch(void* const* d_in, const int* in_sizes, int n_in,
                              void* d_out, int out_size) {
    // Identify inputs by element count (robust to metadata ordering).
    const float* x = nullptr;
    const float* w[4] = {nullptr, nullptr, nullptr, nullptr};
    const float* aw[4] = {nullptr, nullptr, nullptr, nullptr};
    const float* b[4] = {nullptr, nullptr, nullptr, nullptr};
    int iw12 = 1, iaw = 0, ib = 0;
    int Btot = 0;
    for (int i = 0; i < n_in; i++) {
        int sz = in_sizes[i];
        const float* p = (const float*)d_in[i];
        if (sz == 24 * 13 * 64) {
            w[0] = p;
        } else if (sz == 24 * 64 * 64) {
            if (iw12 < 3) w[iw12++] = p;
        } else if (sz == 24 * 64 * 65) {
            w[3] = p;
        } else if (sz == 24 * 24) {
            if (iaw < 4) aw[iaw++] = p;
        } else if (sz == 64) {
            if (ib < 3) b[ib++] = p;
        } else if (sz == 65) {
            b[3] = p;
        } else {
            x = p;
            Btot = sz / (NJ * 13);
        }
    }

    (void)cudaFuncSetAttribute(gnn_fused, cudaFuncAttributeMaxDynamicSharedMemorySize, SMEM_BYTES);

    uint4 *wf0, *wf1, *wf2, *wf3;
    cudaGetSymbolAddress((void**)&wf0, g_wf0);
    cudaGetSymbolAddress((void**)&wf1, g_wf1);
    cudaGetSymbolAddress((void**)&wf2, g_wf2);
    cudaGetSymbolAddress((void**)&wf3, g_wf3);

    prep_frag<<<(NJ * 1 * 8 * 32 + 255) / 256, 256>>>(w[0], wf0, 13, 64, 1, 8);
    prep_frag<<<(NJ * 4 * 8 * 32 + 255) / 256, 256>>>(w[1], wf1, 64, 64, 4, 8);
    prep_frag<<<(NJ * 4 * 8 * 32 + 255) / 256, 256>>>(w[2], wf2, 64, 64, 4, 8);
    prep_frag<<<(NJ * 4 * 9 * 32 + 255) / 256, 256>>>(w[3], wf3, 64, 65, 4, 9);

    int blocks = (Btot + TB - 1) / TB;
    gnn_fused<<<blocks, NTHREADS, SMEM_BYTES>>>(
        x,
        aw[0], aw[1], aw[2], aw[3],
        b[0], b[1], b[2], b[3],
        (float*)d_out, Btot);
}

// round 11
// speedup vs baseline: 3.0763x; 1.0100x over previous
#include <cuda_runtime.h>
#include <cuda_fp16.h>

#define NJ 24
#define TB 48                 // samples per block (3 mma M-tiles)
#define MT 3
#define NTHREADS 768
#define LK 72                 // padded fp16 row: 144 B stride (conflict-free ldmatrix)
#define SMEM_BYTES (NJ * TB * LK * 2)   // 165888

typedef unsigned int uint;

__device__ __forceinline__ unsigned smem_u32(const void* p) {
    unsigned r;
    asm("{ .reg .u64 t; cvta.to.shared.u64 t, %1; cvt.u32.u64 %0, t; }" : "=r"(r) : "l"(p));
    return r;
}
__device__ __forceinline__ uint packh(__half a, __half b) {
    __half2 t = __halves2half2(a, b);
    return *reinterpret_cast<uint*>(&t);
}
__device__ __forceinline__ uint packf2(float a, float b) {
    __half2 t = __floats2half2_rn(a, b);
    return *reinterpret_cast<uint*>(&t);
}

// Kinematic-tree adjacency (self + parent + children), CSR. 70 nonzeros.
__constant__ int cPTR[NJ + 1] = {0,4,7,10,13,16,19,22,25,28,33,35,37,40,43,46,48,51,54,57,60,63,66,68,70};
__constant__ int cCOL[70] = {
    0,1,2,3,  1,0,4,  2,0,5,  3,0,6,  4,1,7,  5,2,8,  6,3,9,  7,4,10,
    8,5,11,  9,6,12,13,14,  10,7,  11,8,  12,9,15,  13,9,16,  14,9,17,
    15,12,  16,13,18,  17,14,19,  18,16,20,  19,17,21,  20,18,22,
    21,19,23,  22,20,  23,21};

// Weight fragments, mma.m16n8k16 B-operand per-lane order, nt-major:
// uint4 at ((n*NT + nt)*KT + kt)*32 + lane = {hi0|hi1, hi2|hi3, lo0|lo1, lo2|lo3}.
__device__ uint4 g_wf0[NJ * 8 * 1 * 32];
__device__ uint4 g_wf1[NJ * 8 * 4 * 32];
__device__ uint4 g_wf2[NJ * 8 * 4 * 32];
__device__ uint4 g_wf3[NJ * 9 * 4 * 32];

__global__ void prep_frag(const float* __restrict__ W, uint4* __restrict__ dst,
                          int DIN, int DOUT, int KT, int NT) {
    int idx = blockIdx.x * blockDim.x + threadIdx.x;
    int total = NJ * NT * KT * 32;
    if (idx >= total) return;
    int lane = idx & 31;
    int kt = (idx >> 5) % KT;
    int nt = (idx / (32 * KT)) % NT;
    int n  = idx / (32 * KT * NT);
    int k0 = kt * 16 + (lane & 3) * 2;
    int nc = nt * 8 + (lane >> 2);

    float w[4];
    int ks[4] = {k0, k0 + 1, k0 + 8, k0 + 9};
#pragma unroll
    for (int i = 0; i < 4; i++)
        w[i] = (ks[i] < DIN && nc < DOUT) ? W[(n * DIN + ks[i]) * DOUT + nc] : 0.0f;

    __half h[4], l[4];
#pragma unroll
    for (int i = 0; i < 4; i++) {
        h[i] = __float2half_rn(w[i]);
        l[i] = __float2half_rn(w[i] - __half2float(h[i]));
    }
    uint4 o;
    o.x = packh(h[0], h[1]);
    o.y = packh(h[2], h[3]);
    o.z = packh(l[0], l[1]);
    o.w = packh(l[2], l[3]);
    dst[idx] = o;
}

#define MMA_F16(C, A0, A1, A2, A3, B0, B1)                                      \
    asm volatile(                                                               \
        "mma.sync.aligned.m16n8k16.row.col.f32.f16.f16.f32 "                    \
        "{%0,%1,%2,%3}, {%4,%5,%6,%7}, {%8,%9}, {%0,%1,%2,%3};"                 \
        : "+f"((C)[0]), "+f"((C)[1]), "+f"((C)[2]), "+f"((C)[3])                \
        : "r"(A0), "r"(A1), "r"(A2), "r"(A3), "r"(B0), "r"(B1))

// Build A-fragments in registers from prev-layer LIN: adjacency + bias + relu.
// a[kt][mt][i]: i: 0=(r,c) 1=(r+8,c) 2=(r,c+8) 3=(r+8,c+8); r=lane>>2, c=2(lane&3)+16kt.
template <int KT>
__device__ __forceinline__ void buildA(const float* __restrict__ aw,
                                       const float* __restrict__ bias,
                                       const __half* __restrict__ LIN,
                                       uint a[KT][MT][4], int n, int lane) {
    int r = lane >> 2;
    int cq = (lane & 3) * 2;
    int deg = cPTR[n + 1] - cPTR[n];
    int mm[5]; float vv[5];
#pragma unroll
    for (int e = 0; e < 5; e++) {
        int ei = cPTR[n] + ((e < deg) ? e : 0);
        mm[e] = cCOL[ei];
        vv[e] = (e < deg) ? aw[n * NJ + mm[e]] : 0.0f;
    }
#pragma unroll
    for (int kt = 0; kt < KT; kt++) {
#pragma unroll
        for (int g = 0; g < 2; g++) {
            int c = kt * 16 + cq + g * 8;
            float2 bb = *reinterpret_cast<const float2*>(bias + c);
#pragma unroll
            for (int mt = 0; mt < MT; mt++) {
#pragma unroll
                for (int h = 0; h < 2; h++) {
                    int s = mt * 16 + r + h * 8;
                    float f0 = bb.x, f1 = bb.y;
#pragma unroll
                    for (int e = 0; e < 5; e++) {
                        if (e < deg) {
                            __half2 hv = *reinterpret_cast<const __half2*>(
                                LIN + (mm[e] * TB + s) * LK + c);
                            float2 fv = __half22float2(hv);
                            f0 = fmaf(vv[e], fv.x, f0);
                            f1 = fmaf(vv[e], fv.y, f1);
                        }
                    }
                    f0 = fmaxf(f0, 0.f);
                    f1 = fmaxf(f1, 0.f);
                    a[kt][mt][h + 2 * g] = packf2(f0, f1);
                }
            }
        }
    }
}

// MMA + in-place store: LIN[n] rows <- A (registers) x W fragments. nt outer, kt inner.
template <int KT, int NT>
__device__ __forceinline__ void mma_store(const uint4* __restrict__ wf,
                                          uint a[KT][MT][4],
                                          __half* __restrict__ LIN, int n, int lane) {
    int r = lane >> 2;
    int cq = (lane & 3) * 2;
    const uint4* wp0 = wf + (size_t)(n * NT) * KT * 32 + lane;
#pragma unroll
    for (int nt = 0; nt < NT; nt++) {
        float acc[MT][4];
#pragma unroll
        for (int mt = 0; mt < MT; mt++) {
            acc[mt][0] = 0.f; acc[mt][1] = 0.f; acc[mt][2] = 0.f; acc[mt][3] = 0.f;
        }
        const uint4* wp = wp0 + (size_t)nt * KT * 32;
#pragma unroll
        for (int kt = 0; kt < KT; kt++) {
            uint4 w = wp[kt * 32];
#pragma unroll
            for (int mt = 0; mt < MT; mt++) {
                MMA_F16(acc[mt], a[kt][mt][0], a[kt][mt][1], a[kt][mt][2], a[kt][mt][3], w.x, w.y);
                MMA_F16(acc[mt], a[kt][mt][0], a[kt][mt][1], a[kt][mt][2], a[kt][mt][3], w.z, w.w);
            }
        }
        int col = nt * 8 + cq;
#pragma unroll
        for (int mt = 0; mt < MT; mt++) {
            *reinterpret_cast<__half2*>(&LIN[(n * TB + mt * 16 + r) * LK + col]) =
                __floats2half2_rn(acc[mt][0], acc[mt][1]);
            *reinterpret_cast<__half2*>(&LIN[(n * TB + mt * 16 + r + 8) * LK + col]) =
                __floats2half2_rn(acc[mt][2], acc[mt][3]);
        }
    }
}

// Final adjacency + bias, fp32 out to gmem (dout = 65).
__device__ __forceinline__ void adj_fin(const float* __restrict__ aw,
                                        const float* __restrict__ bias,
                                        const __half* __restrict__ LIN,
                                        float* __restrict__ outp,
                                        int nvalid, int tid) {
    for (int t = tid; t < NJ * 65 * MT; t += NTHREADS) {
        int strip = t / (NJ * 65);
        int rr = t - strip * (NJ * 65);
        int n = rr / 65;
        int j = rr - n * 65;
        int s0 = strip * 16;
        float bb = bias[j];
        float acc[16];
#pragma unroll
        for (int s = 0; s < 16; s++) acc[s] = bb;
        int e1 = cPTR[n + 1];
        for (int e = cPTR[n]; e < e1; e++) {
            int mj = cCOL[e];
            float v = aw[n * NJ + mj];
#pragma unroll
            for (int s = 0; s < 16; s++) {
                float h = __half2float(LIN[(mj * TB + s0 + s) * LK + j]);
                acc[s] = fmaf(v, h, acc[s]);
            }
        }
#pragma unroll
        for (int s = 0; s < 16; s++)
            if (s0 + s < nvalid)
                outp[(size_t)(s0 + s) * (NJ * 65) + n * 65 + j] = acc[s];
    }
}

__global__ __launch_bounds__(NTHREADS, 1)
void gnn_fused(const float* __restrict__ x,
               const float* __restrict__ aw0, const float* __restrict__ aw1,
               const float* __restrict__ aw2, const float* __restrict__ aw3,
               const float* __restrict__ b0, const float* __restrict__ b1,
               const float* __restrict__ b2, const float* __restrict__ b3,
               float* __restrict__ out, int Btot) {
    extern __shared__ char smraw[];
    __half* LIN = reinterpret_cast<__half*>(smraw);
    int tid = threadIdx.x;
    int lane = tid & 31;
    int n = tid >> 5;                // warp = joint
    int B0 = blockIdx.x * TB;
    int nvalid = Btot - B0;
    if (nvalid > TB) nvalid = TB;

    // Stage x tile -> LIN[n][s][0..15] fp16 (root joint masked, cols 13..15 zero).
    for (int i = tid; i < TB * NJ * 16; i += NTHREADS) {
        int s = i / (NJ * 16);
        int rr = i - s * (NJ * 16);
        int nn = rr >> 4;
        int c = rr & 15;
        float v = 0.0f;
        if (s < nvalid && nn != 0 && c < 13)
            v = x[((size_t)(B0 + s) * NJ + nn) * 13 + c];
        LIN[(nn * TB + s) * LK + c] = __float2half_rn(v);
    }
    __syncthreads();

    // ---- Layer 0: warp-local A via ldmatrix (own-joint x), KT=1.
    {
        uint a0[1][MT][4];
        int rowm = lane & 15;
        int kofs = (lane >> 4) << 3;
#pragma unroll
        for (int mt = 0; mt < MT; mt++) {
            unsigned ad = smem_u32(LIN + ((n * TB + mt * 16 + rowm) * LK) + kofs);
            asm volatile("ldmatrix.sync.aligned.m8n8.x4.shared.b16 {%0,%1,%2,%3}, [%4];"
                         : "=r"(a0[0][mt][0]), "=r"(a0[0][mt][1]),
                           "=r"(a0[0][mt][2]), "=r"(a0[0][mt][3]) : "r"(ad));
        }
        mma_store<1, 8>(g_wf0, a0, LIN, n, lane);   // in-place, own-joint rows only
    }
    __syncthreads();

    // ---- Layers 1..3: buildA (gather + adjacency) / sync / mma in-place.
    {
        uint a[4][MT][4];
        buildA<4>(aw0, b0, LIN, a, n, lane);
        __syncthreads();
        mma_store<4, 8>(g_wf1, a, LIN, n, lane);
        __syncthreads();
        buildA<4>(aw1, b1, LIN, a, n, lane);
        __syncthreads();
        mma_store<4, 8>(g_wf2, a, LIN, n, lane);
        __syncthreads();
        buildA<4>(aw2, b2, LIN, a, n, lane);
        __syncthreads();
        mma_store<4, 9>(g_wf3, a, LIN, n, lane);
        __syncthreads();
    }

    adj_fin(aw3, b3, LIN, out + (size_t)B0 * (NJ * 65), nvalid, tid);
}

extern "C" void kernel_launch(void* const* d_in, const int* in_sizes, int n_in,
                              void* d_out, int out_size) {
    // Identify inputs by element count (robust to metadata ordering).
    const float* x = nullptr;
    const float* w[4] = {nullptr, nullptr, nullptr, nullptr};
    const float* aw[4] = {nullptr, nullptr, nullptr, nullptr};
    const float* b[4] = {nullptr, nullptr, nullptr, nullptr};
    int iw12 = 1, iaw = 0, ib = 0;
    int Btot = 0;
    for (int i = 0; i < n_in; i++) {
        int sz = in_sizes[i];
        const float* p = (const float*)d_in[i];
        if (sz == 24 * 13 * 64) {
            w[0] = p;
        } else if (sz == 24 * 64 * 64) {
            if (iw12 < 3) w[iw12++] = p;
        } else if (sz == 24 * 64 * 65) {
            w[3] = p;
        } else if (sz == 24 * 24) {
            if (iaw < 4) aw[iaw++] = p;
        } else if (sz == 64) {
            if (ib < 3) b[ib++] = p;
        } else if (sz == 65) {
            b[3] = p;
        } else {
            x = p;
            Btot = sz / (NJ * 13);
        }
    }

    (void)cudaFuncSetAttribute(gnn_fused, cudaFuncAttributeMaxDynamicSharedMemorySize, SMEM_BYTES);

    uint4 *wf0, *wf1, *wf2, *wf3;
    cudaGetSymbolAddress((void**)&wf0, g_wf0);
    cudaGetSymbolAddress((void**)&wf1, g_wf1);
    cudaGetSymbolAddress((void**)&wf2, g_wf2);
    cudaGetSymbolAddress((void**)&wf3, g_wf3);

    prep_frag<<<(NJ * 8 * 1 * 32 + 255) / 256, 256>>>(w[0], wf0, 13, 64, 1, 8);
    prep_frag<<<(NJ * 8 * 4 * 32 + 255) / 256, 256>>>(w[1], wf1, 64, 64, 4, 8);
    prep_frag<<<(NJ * 8 * 4 * 32 + 255) / 256, 256>>>(w[2], wf2, 64, 64, 4, 8);
    prep_frag<<<(NJ * 9 * 4 * 32 + 255) / 256, 256>>>(w[3], wf3, 64, 65, 4, 9);

    int blocks = (Btot + TB - 1) / TB;
    gnn_fused<<<blocks, NTHREADS, SMEM_BYTES>>>(
        x,
        aw[0], aw[1], aw[2], aw[3],
        b[0], b[1], b[2], b[3],
        (float*)d_out, Btot);
}

// round 13
// speedup vs baseline: 3.1341x; 1.0188x over previous
#include <cuda_runtime.h>
#include <cuda_fp16.h>

#define NJ 24
#define TB 32                 // samples per block (2 mma M-tiles)
#define MT 2
#define NTHREADS 768
#define LK 72                 // fp32 row stride (288 B); holds 65-col layer-3 output
#define SMEM_BYTES (NJ * TB * LK * 4)   // 221184

typedef unsigned int uint;
typedef unsigned long long ull;

__device__ __forceinline__ unsigned smem_u32(const void* p) {
    unsigned r;
    asm("{ .reg .u64 t; cvta.to.shared.u64 t, %1; cvt.u32.u64 %0, t; }" : "=r"(r) : "l"(p));
    return r;
}
__device__ __forceinline__ uint packh(__half a, __half b) {
    __half2 t = __halves2half2(a, b);
    return *reinterpret_cast<uint*>(&t);
}
__device__ __forceinline__ ull pack2(float lo, float hi) {
    ull r; asm("mov.b64 %0, {%1, %2};" : "=l"(r) : "f"(lo), "f"(hi)); return r;
}
__device__ __forceinline__ ull fma2(ull a, ull b, ull c) {
    ull d; asm("fma.rn.f32x2 %0, %1, %2, %3;" : "=l"(d) : "l"(a), "l"(b), "l"(c)); return d;
}
// relu + pack fp32x2 -> fp16x2 (unpack is register renaming; F2FP does the pack)
__device__ __forceinline__ uint relu_pack(ull v) {
    float lo, hi;
    asm("mov.b64 {%0, %1}, %2;" : "=f"(lo), "=f"(hi) : "l"(v));
    __half2 t = __floats2half2_rn(fmaxf(lo, 0.f), fmaxf(hi, 0.f));
    return *reinterpret_cast<uint*>(&t);
}

// Kinematic-tree adjacency (self + parent + children), CSR. 70 nonzeros.
__constant__ int cPTR[NJ + 1] = {0,4,7,10,13,16,19,22,25,28,33,35,37,40,43,46,48,51,54,57,60,63,66,68,70};
__constant__ int cCOL[70] = {
    0,1,2,3,  1,0,4,  2,0,5,  3,0,6,  4,1,7,  5,2,8,  6,3,9,  7,4,10,
    8,5,11,  9,6,12,13,14,  10,7,  11,8,  12,9,15,  13,9,16,  14,9,17,
    15,12,  16,13,18,  17,14,19,  18,16,20,  19,17,21,  20,18,22,
    21,19,23,  22,20,  23,21};

// Weight fragments, mma.m16n8k16 B-operand per-lane order, nt-major:
// uint4 at ((n*NT + nt)*KT + kt)*32 + lane = {hi0|hi1, hi2|hi3, lo0|lo1, lo2|lo3}.
__device__ uint4 g_wf0[NJ * 8 * 1 * 32];
__device__ uint4 g_wf1[NJ * 8 * 4 * 32];
__device__ uint4 g_wf2[NJ * 8 * 4 * 32];
__device__ uint4 g_wf3[NJ * 9 * 4 * 32];

__global__ void prep_frag(const float* __restrict__ W, uint4* __restrict__ dst,
                          int DIN, int DOUT, int KT, int NT) {
    int idx = blockIdx.x * blockDim.x + threadIdx.x;
    int total = NJ * NT * KT * 32;
    if (idx >= total) return;
    int lane = idx & 31;
    int kt = (idx >> 5) % KT;
    int nt = (idx / (32 * KT)) % NT;
    int n  = idx / (32 * KT * NT);
    int k0 = kt * 16 + (lane & 3) * 2;
    int nc = nt * 8 + (lane >> 2);

    float w[4];
    int ks[4] = {k0, k0 + 1, k0 + 8, k0 + 9};
#pragma unroll
    for (int i = 0; i < 4; i++)
        w[i] = (ks[i] < DIN && nc < DOUT) ? W[(n * DIN + ks[i]) * DOUT + nc] : 0.0f;

    __half h[4], l[4];
#pragma unroll
    for (int i = 0; i < 4; i++) {
        h[i] = __float2half_rn(w[i]);
        l[i] = __float2half_rn(w[i] - __half2float(h[i]));
    }
    uint4 o;
    o.x = packh(h[0], h[1]);
    o.y = packh(h[2], h[3]);
    o.z = packh(l[0], l[1]);
    o.w = packh(l[2], l[3]);
    dst[idx] = o;
}

#define MMA_F16(C, A0, A1, A2, A3, B0, B1)                                      \
    asm volatile(                                                               \
        "mma.sync.aligned.m16n8k16.row.col.f32.f16.f16.f32 "                    \
        "{%0,%1,%2,%3}, {%4,%5,%6,%7}, {%8,%9}, {%0,%1,%2,%3};"                 \
        : "+f"((C)[0]), "+f"((C)[1]), "+f"((C)[2]), "+f"((C)[3])                \
        : "r"(A0), "r"(A1), "r"(A2), "r"(A3), "r"(B0), "r"(B1))

// Build A-fragments from fp32 LIN: adjacency(aw) + bias + relu -> fp16 frags.
// a[kt][mt][i]: i: 0=(r,c) 1=(r+8,c) 2=(r,c+8) 3=(r+8,c+8); r=lane>>2, c=2(lane&3)+16kt.
// Zero F2F: LDS.64 float2 + fma2 (acc init = packed bias), relu+F2FP at the end.
template <int KT>
__device__ __forceinline__ void buildA(const float* __restrict__ aw,
                                       const float* __restrict__ bias,
                                       const float* __restrict__ LIN,
                                       uint a[KT][MT][4], int n, int lane) {
    int r = lane >> 2;
    int cq = (lane & 3) * 2;
    int deg = cPTR[n + 1] - cPTR[n];
    int mm[5]; float vv[5];
#pragma unroll
    for (int e = 0; e < 5; e++) {
        int ei = cPTR[n] + ((e < deg) ? e : 0);
        mm[e] = cCOL[ei];
        vv[e] = (e < deg) ? aw[n * NJ + mm[e]] : 0.0f;
    }
#pragma unroll
    for (int kt = 0; kt < KT; kt++) {
#pragma unroll
        for (int g = 0; g < 2; g++) {
            int c = kt * 16 + cq + g * 8;
            float2 bb = *reinterpret_cast<const float2*>(bias + c);
            ull binit = pack2(bb.x, bb.y);
#pragma unroll
            for (int mt = 0; mt < MT; mt++) {
#pragma unroll
                for (int h = 0; h < 2; h++) {
                    int s = mt * 16 + r + h * 8;
                    ull acc = binit;
#pragma unroll
                    for (int e = 0; e < 5; e++) {
                        if (e < deg) {
                            ull hv = *reinterpret_cast<const ull*>(
                                LIN + (mm[e] * TB + s) * LK + c);      // LDS.64
                            acc = fma2(pack2(vv[e], vv[e]), hv, acc);
                        }
                    }
                    a[kt][mt][h + 2 * g] = relu_pack(acc);
                }
            }
        }
    }
}

// MMA + store fp32 LIN (own joint rows). nt outer, kt inner.
template <int KT, int NT>
__device__ __forceinline__ void mma_store(const uint4* __restrict__ wf,
                                          uint a[KT][MT][4],
                                          float* __restrict__ LIN, int n, int lane) {
    int r = lane >> 2;
    int cq = (lane & 3) * 2;
    const uint4* wp0 = wf + (size_t)(n * NT) * KT * 32 + lane;
#pragma unroll
    for (int nt = 0; nt < NT; nt++) {
        float acc[MT][4];
#pragma unroll
        for (int mt = 0; mt < MT; mt++) {
            acc[mt][0] = 0.f; acc[mt][1] = 0.f; acc[mt][2] = 0.f; acc[mt][3] = 0.f;
        }
        const uint4* wp = wp0 + (size_t)nt * KT * 32;
#pragma unroll
        for (int kt = 0; kt < KT; kt++) {
            uint4 w = wp[kt * 32];
#pragma unroll
            for (int mt = 0; mt < MT; mt++) {
                MMA_F16(acc[mt], a[kt][mt][0], a[kt][mt][1], a[kt][mt][2], a[kt][mt][3], w.x, w.y);
                MMA_F16(acc[mt], a[kt][mt][0], a[kt][mt][1], a[kt][mt][2], a[kt][mt][3], w.z, w.w);
            }
        }
        int col = nt * 8 + cq;
#pragma unroll
        for (int mt = 0; mt < MT; mt++) {
            *reinterpret_cast<float2*>(&LIN[(n * TB + mt * 16 + r) * LK + col]) =
                make_float2(acc[mt][0], acc[mt][1]);
            *reinterpret_cast<float2*>(&LIN[(n * TB + mt * 16 + r + 8) * LK + col]) =
                make_float2(acc[mt][2], acc[mt][3]);
        }
    }
}

// Final adjacency + bias, fp32 out to gmem (dout = 65).
__device__ __forceinline__ void adj_fin(const float* __restrict__ aw,
                                        const float* __restrict__ bias,
                                        const float* __restrict__ LIN,
                                        float* __restrict__ outp,
                                        int nvalid, int tid) {
    for (int t = tid; t < NJ * 65 * MT; t += NTHREADS) {
        int strip = t / (NJ * 65);
        int rr = t - strip * (NJ * 65);
        int n = rr / 65;
        int j = rr - n * 65;
        int s0 = strip * 16;
        float bb = bias[j];
        float acc[16];
#pragma unroll
        for (int s = 0; s < 16; s++) acc[s] = bb;
        int e1 = cPTR[n + 1];
        for (int e = cPTR[n]; e < e1; e++) {
            int mj = cCOL[e];
            float v = aw[n * NJ + mj];
#pragma unroll
            for (int s = 0; s < 16; s++)
                acc[s] = fmaf(v, LIN[(mj * TB + s0 + s) * LK + j], acc[s]);
        }
#pragma unroll
        for (int s = 0; s < 16; s++)
            if (s0 + s < nvalid)
                outp[(size_t)(s0 + s) * (NJ * 65) + n * 65 + j] = acc[s];
    }
}

__global__ __launch_bounds__(NTHREADS, 1)
void gnn_fused(const float* __restrict__ x,
               const float* __restrict__ aw0, const float* __restrict__ aw1,
               const float* __restrict__ aw2, const float* __restrict__ aw3,
               const float* __restrict__ b0, const float* __restrict__ b1,
               const float* __restrict__ b2, const float* __restrict__ b3,
               float* __restrict__ out, int Btot) {
    extern __shared__ char smraw[];
    float* LIN = reinterpret_cast<float*>(smraw);
    __half* XH = reinterpret_cast<__half*>(smraw);    // layer-0 staging view
    int tid = threadIdx.x;
    int lane = tid & 31;
    int n = tid >> 5;                // warp = joint
    int B0 = blockIdx.x * TB;
    int nvalid = Btot - B0;
    if (nvalid > TB) nvalid = TB;

    // Stage x as fp16 into the low 16 halves of each fp32 row (root masked, cols 13..15 zero).
    for (int i = tid; i < TB * NJ * 16; i += NTHREADS) {
        int s = i / (NJ * 16);
        int rr = i - s * (NJ * 16);
        int nn = rr >> 4;
        int c = rr & 15;
        float v = 0.0f;
        if (s < nvalid && nn != 0 && c < 13)
            v = x[((size_t)(B0 + s) * NJ + nn) * 13 + c];
        XH[((nn * TB + s) * LK) * 2 + c] = __float2half_rn(v);
    }
    __syncthreads();

    // ---- Layer 0: ldmatrix own-joint x frags, then mma overwrites own rows in place.
    {
        uint a0[1][MT][4];
        int rowm = lane & 15;
        int kofs = (lane >> 4) << 3;
#pragma unroll
        for (int mt = 0; mt < MT; mt++) {
            unsigned ad = smem_u32(XH + ((n * TB + mt * 16 + rowm) * LK) * 2 + kofs);
            asm volatile("ldmatrix.sync.aligned.m8n8.x4.shared.b16 {%0,%1,%2,%3}, [%4];"
                         : "=r"(a0[0][mt][0]), "=r"(a0[0][mt][1]),
                           "=r"(a0[0][mt][2]), "=r"(a0[0][mt][3]) : "r"(ad));
        }
        mma_store<1, 8>(g_wf0, a0, LIN, n, lane);
    }
    __syncthreads();

    // ---- Layers 1..3: buildA (fp32 gather + adjacency) / sync / mma in-place.
    {
        uint a[4][MT][4];
        buildA<4>(aw0, b0, LIN, a, n, lane);
        __syncthreads();
        mma_store<4, 8>(g_wf1, a, LIN, n, lane);
        __syncthreads();
        buildA<4>(aw1, b1, LIN, a, n, lane);
        __syncthreads();
        mma_store<4, 8>(g_wf2, a, LIN, n, lane);
        __syncthreads();
        buildA<4>(aw2, b2, LIN, a, n, lane);
        __syncthreads();
        mma_store<4, 9>(g_wf3, a, LIN, n, lane);
        __syncthreads();
    }

    adj_fin(aw3, b3, LIN, out + (size_t)B0 * (NJ * 65), nvalid, tid);
}

extern "C" void kernel_launch(void* const* d_in, const int* in_sizes, int n_in,
                              void* d_out, int out_size) {
    // Identify inputs by element count (robust to metadata ordering).
    const float* x = nullptr;
    const float* w[4] = {nullptr, nullptr, nullptr, nullptr};
    const float* aw[4] = {nullptr, nullptr, nullptr, nullptr};
    const float* b[4] = {nullptr, nullptr, nullptr, nullptr};
    int iw12 = 1, iaw = 0, ib = 0;
    int Btot = 0;
    for (int i = 0; i < n_in; i++) {
        int sz = in_sizes[i];
        const float* p = (const float*)d_in[i];
        if (sz == 24 * 13 * 64) {
            w[0] = p;
        } else if (sz == 24 * 64 * 64) {
            if (iw12 < 3) w[iw12++] = p;
        } else if (sz == 24 * 64 * 65) {
            w[3] = p;
        } else if (sz == 24 * 24) {
            if (iaw < 4) aw[iaw++] = p;
        } else if (sz == 64) {
            if (ib < 3) b[ib++] = p;
        } else if (sz == 65) {
            b[3] = p;
        } else {
            x = p;
            Btot = sz / (NJ * 13);
        }
    }

    (void)cudaFuncSetAttribute(gnn_fused, cudaFuncAttributeMaxDynamicSharedMemorySize, SMEM_BYTES);

    uint4 *wf0, *wf1, *wf2, *wf3;
    cudaGetSymbolAddress((void**)&wf0, g_wf0);
    cudaGetSymbolAddress((void**)&wf1, g_wf1);
    cudaGetSymbolAddress((void**)&wf2, g_wf2);
    cudaGetSymbolAddress((void**)&wf3, g_wf3);

    prep_frag<<<(NJ * 8 * 1 * 32 + 255) / 256, 256>>>(w[0], wf0, 13, 64, 1, 8);
    prep_frag<<<(NJ * 8 * 4 * 32 + 255) / 256, 256>>>(w[1], wf1, 64, 64, 4, 8);
    prep_frag<<<(NJ * 8 * 4 * 32 + 255) / 256, 256>>>(w[2], wf2, 64, 64, 4, 8);
    prep_frag<<<(NJ * 9 * 4 * 32 + 255) / 256, 256>>>(w[3], wf3, 64, 65, 4, 9);

    int blocks = (Btot + TB - 1) / TB;
    gnn_fused<<<blocks, NTHREADS, SMEM_BYTES>>>(
        x,
        aw[0], aw[1], aw[2], aw[3],
        b[0], b[1], b[2], b[3],
        (float*)d_out, Btot);
}